// round 13
// baseline (speedup 1.0000x reference)
#include <cuda_runtime.h>
#include <math_constants.h>

__device__ unsigned g_maxu;   // ordered-uint global max; reset by last block each call
__device__ unsigned g_count;  // block finish counter; reset by last block each call

__device__ __forceinline__ unsigned order_f32(float f) {
    unsigned u = __float_as_uint(f);
    return (u & 0x80000000u) ? ~u : (u | 0x80000000u);
}
__device__ __forceinline__ float unorder_f32(unsigned u) {
    return __uint_as_float((u & 0x80000000u) ? (u ^ 0x80000000u) : ~u);
}
__device__ __forceinline__ void top2_update(float& t1, float& t2, float v) {
    t2 = fmaxf(t2, fminf(t1, v));
    t1 = fmaxf(t1, v);
}

// Block = 448 threads = 14 warps = 2 rows x 7 heads. Each warp does exactly
// ONE (row, head) scan (the protected R6 load batch), one barrier, then a
// parallel 14-thread softmax epilogue. No tail kernel, no task serialization.
template<int NV4>   // NV4 = C/4
__global__ __launch_bounds__(448) void fused2_kernel(
    const float* __restrict__ o1, const float* __restrict__ o2,
    const float* __restrict__ o3, const float* __restrict__ o4,
    const float* __restrict__ o5, const float* __restrict__ o6,
    const float* __restrict__ mimic,
    const int* __restrict__ targets,
    float* __restrict__ out_thresh,   // [N,7]
    float* __restrict__ out_max,      // out[0]
    int C, int N)
{
    const int wid  = threadIdx.x >> 5;      // 0..13
    const int lane = threadIdx.x & 31;
    const int rowbase = blockIdx.x << 1;
    const int nrows = min(2, N - rowbase);
    const int ntask = nrows * 7;

    __shared__ float s_margin[14];
    __shared__ float s_top1[14];

    if (wid < ntask) {
        const int r   = wid / 7;             // 0..1
        const int h   = wid - r * 7;         // 0..6
        const int row = rowbase + r;

        const float* heads[7] = {o1, o2, o3, o4, o5, o6, mimic};
        const float* p = heads[h] + (size_t)row * (size_t)C;
        const float4* p4 = (const float4*)p;

        const int tgt = targets[row];
        float tval = (lane == 0) ? __ldg(p + tgt) : 0.0f;

        constexpr int K = (NV4 + 31) / 32;   // 8 for NV4=250
        float4 v[K];
        #pragma unroll
        for (int k = 0; k < K; ++k) {
            int idx = lane + 32 * k;
            if (32 * k + 31 < NV4 || idx < NV4)
                v[k] = __ldcs(p4 + idx);
            else
                v[k] = make_float4(-CUDART_INF_F, -CUDART_INF_F,
                                   -CUDART_INF_F, -CUDART_INF_F);
        }

        float t1 = -CUDART_INF_F, t2 = -CUDART_INF_F;
        #pragma unroll
        for (int k = 0; k < K; ++k) {
            top2_update(t1, t2, v[k].x);
            top2_update(t1, t2, v[k].y);
            top2_update(t1, t2, v[k].z);
            top2_update(t1, t2, v[k].w);
        }

        #pragma unroll
        for (int off = 16; off; off >>= 1) {
            float u1 = __shfl_down_sync(0xFFFFFFFFu, t1, off);
            float u2 = __shfl_down_sync(0xFFFFFFFFu, t2, off);
            t2 = fmaxf(fmaxf(t2, u2), fminf(t1, u1));
            t1 = fmaxf(t1, u1);
        }

        if (lane == 0) {
            s_margin[wid] = (tval == t1) ? (t1 - t2) * 0.5f : 0.0f;
            s_top1[wid]   = (h < 6) ? t1 : -CUDART_INF_F;
        }
    }
    __syncthreads();

    // threads 0..ntask-1: per-row softmax from smem, coalesced store
    if (threadIdx.x < (unsigned)ntask) {
        const int r = threadIdx.x / 7;
        const float* mp = s_margin + r * 7;
        float mx = -CUDART_INF_F;
        #pragma unroll
        for (int h = 0; h < 7; ++h) mx = fmaxf(mx, mp[h]);
        float sum = 0.0f;
        #pragma unroll
        for (int h = 0; h < 7; ++h) sum += __expf(mp[h] - mx);
        float mine = __expf(s_margin[threadIdx.x] - mx);
        out_thresh[(size_t)rowbase * 7 + threadIdx.x] = mine / sum;
    }

    // warp 0: block max -> one RED.MAX; last-done block publishes out[0]
    if (wid == 0) {
        float m = (lane < ntask) ? s_top1[lane] : -CUDART_INF_F;
        #pragma unroll
        for (int off = 16; off; off >>= 1)
            m = fmaxf(m, __shfl_down_sync(0xFFFFFFFFu, m, off));
        if (lane == 0) {
            atomicMax(&g_maxu, order_f32(m));
            __threadfence();
            unsigned old = atomicAdd(&g_count, 1u);
            if (old == gridDim.x - 1) {
                out_max[0] = unorder_f32(g_maxu);
                g_maxu  = 0u;   // deterministic reset for next graph replay
                g_count = 0u;
            }
        }
    }
}

// Generic fallback (runtime C), same structure.
__global__ __launch_bounds__(448) void fused2_kernel_gen(
    const float* __restrict__ o1, const float* __restrict__ o2,
    const float* __restrict__ o3, const float* __restrict__ o4,
    const float* __restrict__ o5, const float* __restrict__ o6,
    const float* __restrict__ mimic,
    const int* __restrict__ targets,
    float* __restrict__ out_thresh, float* __restrict__ out_max,
    int C, int N)
{
    const int wid  = threadIdx.x >> 5;
    const int lane = threadIdx.x & 31;
    const int rowbase = blockIdx.x << 1;
    const int nrows = min(2, N - rowbase);
    const int ntask = nrows * 7;

    __shared__ float s_margin[14];
    __shared__ float s_top1[14];

    if (wid < ntask) {
        const int r   = wid / 7;
        const int h   = wid - r * 7;
        const int row = rowbase + r;

        const float* heads[7] = {o1, o2, o3, o4, o5, o6, mimic};
        const float* p = heads[h] + (size_t)row * (size_t)C;

        const int tgt = targets[row];
        float tval = (lane == 0) ? __ldg(p + tgt) : 0.0f;

        float t1 = -CUDART_INF_F, t2 = -CUDART_INF_F;
        const int nv4 = C >> 2;
        const float4* p4 = (const float4*)p;
        for (int i = lane; i < nv4; i += 32) {
            float4 v = __ldcs(p4 + i);
            top2_update(t1, t2, v.x); top2_update(t1, t2, v.y);
            top2_update(t1, t2, v.z); top2_update(t1, t2, v.w);
        }
        for (int i = (nv4 << 2) + lane; i < C; i += 32)
            top2_update(t1, t2, p[i]);

        #pragma unroll
        for (int off = 16; off; off >>= 1) {
            float u1 = __shfl_down_sync(0xFFFFFFFFu, t1, off);
            float u2 = __shfl_down_sync(0xFFFFFFFFu, t2, off);
            t2 = fmaxf(fmaxf(t2, u2), fminf(t1, u1));
            t1 = fmaxf(t1, u1);
        }

        if (lane == 0) {
            s_margin[wid] = (tval == t1) ? (t1 - t2) * 0.5f : 0.0f;
            s_top1[wid]   = (h < 6) ? t1 : -CUDART_INF_F;
        }
    }
    __syncthreads();

    if (threadIdx.x < (unsigned)ntask) {
        const int r = threadIdx.x / 7;
        const float* mp = s_margin + r * 7;
        float mx = -CUDART_INF_F;
        #pragma unroll
        for (int h = 0; h < 7; ++h) mx = fmaxf(mx, mp[h]);
        float sum = 0.0f;
        #pragma unroll
        for (int h = 0; h < 7; ++h) sum += __expf(mp[h] - mx);
        float mine = __expf(s_margin[threadIdx.x] - mx);
        out_thresh[(size_t)rowbase * 7 + threadIdx.x] = mine / sum;
    }

    if (wid == 0) {
        float m = (lane < ntask) ? s_top1[lane] : -CUDART_INF_F;
        #pragma unroll
        for (int off = 16; off; off >>= 1)
            m = fmaxf(m, __shfl_down_sync(0xFFFFFFFFu, m, off));
        if (lane == 0) {
            atomicMax(&g_maxu, order_f32(m));
            __threadfence();
            unsigned old = atomicAdd(&g_count, 1u);
            if (old == gridDim.x - 1) {
                out_max[0] = unorder_f32(g_maxu);
                g_maxu  = 0u;
                g_count = 0u;
            }
        }
    }
}

extern "C" void kernel_launch(void* const* d_in, const int* in_sizes, int n_in,
                              void* d_out, int out_size) {
    const float* o1    = (const float*)d_in[0];
    const float* o2    = (const float*)d_in[1];
    const float* o3    = (const float*)d_in[2];
    const float* o4    = (const float*)d_in[3];
    const float* o5    = (const float*)d_in[4];
    const float* o6    = (const float*)d_in[5];
    const float* mimic = (const float*)d_in[6];
    const int*   tgt   = (const int*)d_in[7];

    const int N = in_sizes[7];            // 16384 rows
    const int C = in_sizes[0] / N;        // 1000 classes

    float* out = (float*)d_out;           // [0]=max_preds, [1..]=thresholds [N,7]

    const int grid = (N + 1) >> 1;        // 8192 blocks, 2 rows each

    if (C == 1000) {
        fused2_kernel<250><<<grid, 448>>>(o1, o2, o3, o4, o5, o6, mimic, tgt,
                                          out + 1, out, C, N);
    } else {
        fused2_kernel_gen<<<grid, 448>>>(o1, o2, o3, o4, o5, o6, mimic, tgt,
                                         out + 1, out, C, N);
    }
}

// round 15
// speedup vs baseline: 1.1157x; 1.1157x over previous
#include <cuda_runtime.h>
#include <math_constants.h>

#define MAX_N 65536
__device__ float    g_margin[MAX_N * 7];  // pre-scaled margins (m/2); overwritten each call
__device__ unsigned g_maxu;               // ordered-uint global max; reset by finalize each call

__device__ __forceinline__ unsigned order_f32(float f) {
    unsigned u = __float_as_uint(f);
    return (u & 0x80000000u) ? ~u : (u | 0x80000000u);
}
__device__ __forceinline__ float unorder_f32(unsigned u) {
    return __uint_as_float((u & 0x80000000u) ? (u ^ 0x80000000u) : ~u);
}
__device__ __forceinline__ void top2_update(float& t1, float& t2, float v) {
    t2 = fmaxf(t2, fminf(t1, v));
    t1 = fmaxf(t1, v);
}
// Scalar store with L2 evict-last cache-hint policy (legal ptx form on sm_103)
__device__ __forceinline__ void st_evict_last(float* p, float v) {
    asm volatile(
        "{\n\t"
        ".reg .b64 pol;\n\t"
        "createpolicy.fractional.L2::evict_last.b64 pol, 1.0;\n\t"
        "st.global.L2::cache_hint.f32 [%0], %1, pol;\n\t"
        "}"
        :: "l"(p), "f"(v) : "memory");
}

// ---------- Kernel A (R6/R10 structure, protected): one warp per (row, head) ----------
template<int NV4>   // NV4 = C/4
__global__ __launch_bounds__(256) void scan_kernel(
    const float* __restrict__ o1, const float* __restrict__ o2,
    const float* __restrict__ o3, const float* __restrict__ o4,
    const float* __restrict__ o5, const float* __restrict__ o6,
    const float* __restrict__ mimic,
    const int* __restrict__ targets,
    int C, int N)
{
    const int wid  = threadIdx.x >> 5;
    const int lane = threadIdx.x & 31;
    const int gw   = (blockIdx.x << 3) + wid;
    const int total = N * 7;

    __shared__ float s_top1[8];
    s_top1[wid] = -CUDART_INF_F;

    if (gw < total) {
        const int row = gw / 7;
        const int h   = gw - row * 7;

        const float* heads[7] = {o1, o2, o3, o4, o5, o6, mimic};
        const float* p = heads[h] + (size_t)row * (size_t)C;
        const float4* p4 = (const float4*)p;

        const int tgt = targets[row];
        float tval = (lane == 0) ? __ldg(p + tgt) : 0.0f;

        constexpr int K = (NV4 + 31) / 32;   // 8 for NV4=250
        float4 v[K];
        #pragma unroll
        for (int k = 0; k < K; ++k) {
            int idx = lane + 32 * k;
            if (32 * k + 31 < NV4 || idx < NV4)
                v[k] = __ldcs(p4 + idx);
            else
                v[k] = make_float4(-CUDART_INF_F, -CUDART_INF_F,
                                   -CUDART_INF_F, -CUDART_INF_F);
        }

        float t1 = -CUDART_INF_F, t2 = -CUDART_INF_F;
        #pragma unroll
        for (int k = 0; k < K; ++k) {
            top2_update(t1, t2, v[k].x);
            top2_update(t1, t2, v[k].y);
            top2_update(t1, t2, v[k].z);
            top2_update(t1, t2, v[k].w);
        }

        #pragma unroll
        for (int off = 16; off; off >>= 1) {
            float u1 = __shfl_down_sync(0xFFFFFFFFu, t1, off);
            float u2 = __shfl_down_sync(0xFFFFFFFFu, t2, off);
            t2 = fmaxf(fmaxf(t2, u2), fminf(t1, u1));
            t1 = fmaxf(t1, u1);
        }

        if (lane == 0) {
            st_evict_last(&g_margin[gw], (tval == t1) ? (t1 - t2) * 0.5f : 0.0f);
            if (h < 6) s_top1[wid] = t1;
        }
    }
    __syncthreads();

    if (threadIdx.x == 0) {
        float bm = s_top1[0];
        #pragma unroll
        for (int w = 1; w < 8; ++w) bm = fmaxf(bm, s_top1[w]);
        atomicMax(&g_maxu, order_f32(bm));   // fire-and-forget RED.MAX
    }
    asm volatile("griddepcontrol.launch_dependents;");
}

__global__ __launch_bounds__(256) void scan_kernel_gen(
    const float* __restrict__ o1, const float* __restrict__ o2,
    const float* __restrict__ o3, const float* __restrict__ o4,
    const float* __restrict__ o5, const float* __restrict__ o6,
    const float* __restrict__ mimic,
    const int* __restrict__ targets,
    int C, int N)
{
    const int wid  = threadIdx.x >> 5;
    const int lane = threadIdx.x & 31;
    const int gw   = (blockIdx.x << 3) + wid;
    const int total = N * 7;

    __shared__ float s_top1[8];
    s_top1[wid] = -CUDART_INF_F;

    if (gw < total) {
        const int row = gw / 7;
        const int h   = gw - row * 7;
        const float* heads[7] = {o1, o2, o3, o4, o5, o6, mimic};
        const float* p = heads[h] + (size_t)row * (size_t)C;

        const int tgt = targets[row];
        float tval = (lane == 0) ? __ldg(p + tgt) : 0.0f;

        float t1 = -CUDART_INF_F, t2 = -CUDART_INF_F;
        const int nv4 = C >> 2;
        const float4* p4 = (const float4*)p;
        for (int i = lane; i < nv4; i += 32) {
            float4 v = __ldcs(p4 + i);
            top2_update(t1, t2, v.x); top2_update(t1, t2, v.y);
            top2_update(t1, t2, v.z); top2_update(t1, t2, v.w);
        }
        for (int i = (nv4 << 2) + lane; i < C; i += 32)
            top2_update(t1, t2, p[i]);

        #pragma unroll
        for (int off = 16; off; off >>= 1) {
            float u1 = __shfl_down_sync(0xFFFFFFFFu, t1, off);
            float u2 = __shfl_down_sync(0xFFFFFFFFu, t2, off);
            t2 = fmaxf(fmaxf(t2, u2), fminf(t1, u1));
            t1 = fmaxf(t1, u1);
        }
        if (lane == 0) {
            st_evict_last(&g_margin[gw], (tval == t1) ? (t1 - t2) * 0.5f : 0.0f);
            if (h < 6) s_top1[wid] = t1;
        }
    }
    __syncthreads();
    if (threadIdx.x == 0) {
        float bm = s_top1[0];
        #pragma unroll
        for (int w = 1; w < 8; ++w) bm = fmaxf(bm, s_top1[w]);
        atomicMax(&g_maxu, order_f32(bm));
    }
    asm volatile("griddepcontrol.launch_dependents;");
}

// ---------- Kernel B (PDL secondary): thread-per-row softmax, L2-hit loads ----------
__global__ __launch_bounds__(128) void finalize_kernel(
    float* __restrict__ out,          // out[0]=max, out+1 = thresholds [N,7]
    int N)
{
    asm volatile("griddepcontrol.wait;");

    const int row = blockIdx.x * 128 + threadIdx.x;
    if (row < N) {
        const float* mp = g_margin + row * 7;
        float m[7], mx = -CUDART_INF_F;
        #pragma unroll
        for (int h = 0; h < 7; ++h) { m[h] = __ldg(mp + h); mx = fmaxf(mx, m[h]); }
        float e[7], sum = 0.0f;
        #pragma unroll
        for (int h = 0; h < 7; ++h) { e[h] = __expf(m[h] - mx); sum += e[h]; }
        float inv = 1.0f / sum;
        float* o = out + 1 + (size_t)row * 7;
        #pragma unroll
        for (int h = 0; h < 7; ++h) o[h] = e[h] * inv;
    }

    if (blockIdx.x == 0 && threadIdx.x == 0) {
        out[0] = unorder_f32(g_maxu);
        g_maxu = 0u;   // deterministic reset for next graph replay
    }
}

extern "C" void kernel_launch(void* const* d_in, const int* in_sizes, int n_in,
                              void* d_out, int out_size) {
    const float* o1    = (const float*)d_in[0];
    const float* o2    = (const float*)d_in[1];
    const float* o3    = (const float*)d_in[2];
    const float* o4    = (const float*)d_in[3];
    const float* o5    = (const float*)d_in[4];
    const float* o6    = (const float*)d_in[5];
    const float* mimic = (const float*)d_in[6];
    const int*   tgt   = (const int*)d_in[7];

    const int N = in_sizes[7];            // 16384 rows
    const int C = in_sizes[0] / N;        // 1000 classes

    float* out = (float*)d_out;

    const int total_warps = N * 7;                  // 114688
    const int grid = (total_warps + 7) >> 3;        // 14336 blocks

    if (C == 1000) {
        scan_kernel<250><<<grid, 256>>>(o1, o2, o3, o4, o5, o6, mimic, tgt, C, N);
    } else {
        scan_kernel_gen<<<grid, 256>>>(o1, o2, o3, o4, o5, o6, mimic, tgt, C, N);
    }

    // finalize as a PDL secondary: one row per thread, 128 blocks for fast ramp
    cudaLaunchConfig_t cfg = {};
    cfg.gridDim  = dim3((N + 127) >> 7, 1, 1);      // 128 blocks for N=16384
    cfg.blockDim = dim3(128, 1, 1);
    cudaLaunchAttribute attr[1];
    attr[0].id = cudaLaunchAttributeProgrammaticStreamSerialization;
    attr[0].val.programmaticStreamSerializationAllowed = 1;
    cfg.attrs = attr;
    cfg.numAttrs = 1;
    cudaLaunchKernelEx(&cfg, finalize_kernel, out, N);
}